// round 7
// baseline (speedup 1.0000x reference)
#include <cuda_runtime.h>
#include <cuda.h>
#include <cstdint>

// ---------------- scratch (no allocations allowed) ----------------
#define MAX_BLOCKS 2048
__device__ float g_partials[MAX_BLOCKS];
__device__ unsigned int g_ticket = 0;   // last block wraps it back to 0

// ---------------- small PTX helpers ----------------
__device__ __forceinline__ uint32_t smem_u32(const void* p) {
    uint32_t a;
    asm("{ .reg .u64 t; cvta.to.shared.u64 t, %1; cvt.u32.u64 %0, t; }"
        : "=r"(a) : "l"(p));
    return a;
}
#define MBARRIER_INIT(addr, cnt) \
    asm volatile("mbarrier.init.shared.b64 [%0], %1;" :: "r"(addr), "r"(cnt) : "memory")
#define MBARRIER_EXPECT_TX(addr, bytes) \
    asm volatile("mbarrier.arrive.expect_tx.shared.b64 _, [%0], %1;" :: "r"(addr), "r"(bytes) : "memory")
__device__ __forceinline__ void mbar_wait(uint32_t mbar, uint32_t parity) {
    asm volatile(
        "{\n\t"
        ".reg .pred P1;\n\t"
        "WAIT_LOOP_%=:\n\t"
        "mbarrier.try_wait.parity.acquire.cta.shared::cta.b64 P1, [%0], %1, 0x989680;\n\t"
        "@P1 bra.uni WAIT_DONE_%=;\n\t"
        "bra.uni WAIT_LOOP_%=;\n\t"
        "WAIT_DONE_%=:\n\t"
        "}"
        :: "r"(mbar), "r"(parity) : "memory");
}
// TMA tile::gather4 — fetch 4 rows (16B each, boxDim={4,1}) into SMEM (64B).
// dst MUST be 128B aligned.
__device__ __forceinline__ void tma_gather4(uint32_t dst_smem, const void* tmap,
                                            int r0, int r1, int r2, int r3,
                                            uint32_t mbar) {
    asm volatile(
        "cp.async.bulk.tensor.2d.shared::cta.global.tile::gather4.mbarrier::complete_tx::bytes "
        "[%0], [%1, {%2, %3, %4, %5, %6}], [%7];"
        :: "r"(dst_smem), "l"(tmap), "r"(0), "r"(r0), "r"(r1), "r"(r2), "r"(r3),
           "r"(mbar)
        : "memory");
}

// ---------------- shared reduction epilogue ----------------
#define REDUCE_EPILOGUE(acc, out, inv_p)                                        \
    do {                                                                        \
        _Pragma("unroll")                                                       \
        for (int off = 16; off > 0; off >>= 1)                                  \
            acc += __shfl_down_sync(0xffffffffu, acc, off);                     \
        __shared__ float warp_sums_[8];                                         \
        int lane_ = threadIdx.x & 31;                                           \
        int wid_  = threadIdx.x >> 5;                                           \
        if (lane_ == 0) warp_sums_[wid_] = acc;                                 \
        __syncthreads();                                                        \
        __shared__ bool is_last_;                                               \
        if (wid_ == 0) {                                                        \
            float v = (lane_ < 8) ? warp_sums_[lane_] : 0.0f;                   \
            _Pragma("unroll")                                                   \
            for (int off = 4; off > 0; off >>= 1)                               \
                v += __shfl_down_sync(0xffffffffu, v, off);                     \
            if (lane_ == 0) {                                                   \
                g_partials[blockIdx.x] = v;                                     \
                __threadfence();                                                \
                unsigned int done = atomicInc(&g_ticket, gridDim.x - 1);        \
                is_last_ = (done == gridDim.x - 1);                             \
            }                                                                   \
        }                                                                       \
        __syncthreads();                                                        \
        if (is_last_) {                                                         \
            double s = 0.0;                                                     \
            for (int i = threadIdx.x; i < (int)gridDim.x; i += blockDim.x)      \
                s += (double)g_partials[i];                                     \
            __shared__ double dsums_[8];                                        \
            _Pragma("unroll")                                                   \
            for (int off = 16; off > 0; off >>= 1)                              \
                s += __shfl_down_sync(0xffffffffu, s, off);                     \
            if (lane_ == 0) dsums_[wid_] = s;                                   \
            __syncthreads();                                                    \
            if (wid_ == 0) {                                                    \
                double t = (lane_ < 8) ? dsums_[lane_] : 0.0;                   \
                _Pragma("unroll")                                               \
                for (int off = 4; off > 0; off >>= 1)                           \
                    t += __shfl_down_sync(0xffffffffu, t, off);                 \
                if (lane_ == 0) out[0] = (float)(t * (double)inv_p);            \
            }                                                                   \
        }                                                                       \
    } while (0)

// ================= hybrid kernel =================
// Warps 0-3: LDG gathers (L1tex/LSU pipe) over edges [0, L).
// Warps 4-7: TMA gather4 (TMA engine pipe) over edges [L, p),
//            64 edges per warp-batch, 2-stage double buffer per warp.
#define TMA_WARPS 4
#define LDG_WARPS 4
#define STRIDE_PER_LANE 128  // gather4 dst must be 128B aligned; 64B data + 64B pad
#define STAGE_BYTES (32 * STRIDE_PER_LANE)   // 4096 per warp-stage

__global__ void __launch_bounds__(256)
mde_hybrid_kernel(const __grid_constant__ CUtensorMap tmap,
                  const float4* __restrict__ X,
                  const int4* __restrict__ epairs,
                  const float2* __restrict__ wpairs,
                  int npairs_ldg,          // int4 pairs in LDG region
                  int nb_tma,              // 64-edge batches in TMA region
                  const int2* __restrict__ etail,
                  const float* __restrict__ wtail,
                  int tail_lo, int tail_hi, // leftover single edges [lo, hi)
                  float* __restrict__ out, float inv_p) {
    __shared__ __align__(8)   uint64_t mbar[TMA_WARPS * 2];
    __shared__ __align__(128) char tbuf[TMA_WARPS][2][STAGE_BYTES];

    int tid  = threadIdx.x;
    int lane = tid & 31;
    int wid  = tid >> 5;
    float acc = 0.0f;

    if (wid < LDG_WARPS) {
        // ---------- LDG path ----------
        int t = blockIdx.x * (LDG_WARPS * 32) + wid * 32 + lane;
        int stride = gridDim.x * (LDG_WARPS * 32);
        for (int k = t; k < npairs_ldg; k += stride) {
            int4   e = __ldcs(&epairs[k]);
            float2 w = __ldcs(&wpairs[k]);
            float4 a0 = __ldg(&X[e.x]);
            float4 b0 = __ldg(&X[e.y]);
            float4 a1 = __ldg(&X[e.z]);
            float4 b1 = __ldg(&X[e.w]);
            float dx0 = a0.x - b0.x, dy0 = a0.y - b0.y, dz0 = a0.z - b0.z, dw0 = a0.w - b0.w;
            float dx1 = a1.x - b1.x, dy1 = a1.y - b1.y, dz1 = a1.z - b1.z, dw1 = a1.w - b1.w;
            acc = fmaf(w.x, dx0 * dx0 + dy0 * dy0 + dz0 * dz0 + dw0 * dw0, acc);
            acc = fmaf(w.y, dx1 * dx1 + dy1 * dy1 + dz1 * dz1 + dw1 * dw1, acc);
        }
        // leftover single edges (at most 1)
        for (int k = tail_lo + t; k < tail_hi; k += stride) {
            int2 e = __ldg(&etail[k]);
            float4 a = __ldg(&X[e.x]);
            float4 b = __ldg(&X[e.y]);
            float dx = a.x - b.x, dy = a.y - b.y, dz = a.z - b.z, dw = a.w - b.w;
            acc = fmaf(__ldg(&wtail[k]), dx * dx + dy * dy + dz * dz + dw * dw, acc);
        }
    } else {
        // ---------- TMA gather4 path ----------
        int tw = wid - LDG_WARPS;            // 0..3
        uint32_t mb0 = smem_u32(&mbar[tw * 2 + 0]);
        uint32_t mb1 = smem_u32(&mbar[tw * 2 + 1]);
        uint32_t buf0 = smem_u32(&tbuf[tw][0][0]) + (uint32_t)lane * STRIDE_PER_LANE;
        uint32_t buf1 = smem_u32(&tbuf[tw][1][0]) + (uint32_t)lane * STRIDE_PER_LANE;
        if (lane == 0) {
            MBARRIER_INIT(mb0, 1);
            MBARRIER_INIT(mb1, 1);
            asm volatile("fence.proxy.async.shared::cta;" ::: "memory");
        }
        __syncwarp();

        int W  = gridDim.x * TMA_WARPS;
        int gw = blockIdx.x * TMA_WARPS + tw;
        int nlocal = (gw < nb_tma) ? ((nb_tma - 1 - gw) / W + 1) : 0;

        float2 w0, w1;
        auto issue = [&](int bl, uint32_t mb, uint32_t bufaddr, float2& wreg) {
            int gb = gw + bl * W;
            int idx = npairs_ldg + gb * 32 + lane;   // int4 index into edge array
            if (lane == 0) MBARRIER_EXPECT_TX(mb, 32 * 64);
            __syncwarp();
            int4 e = __ldcs(&epairs[idx]);
            wreg = __ldcs(&wpairs[idx]);
            tma_gather4(bufaddr, (const void*)&tmap, e.x, e.y, e.z, e.w, mb);
        };
        auto consume = [&](uint32_t bufaddr, float2 w) {
            const float4* blk = (const float4*)__cvta_shared_to_generic(bufaddr);
            float4 a0 = blk[0], b0 = blk[1], a1 = blk[2], b1 = blk[3];
            float dx0 = a0.x - b0.x, dy0 = a0.y - b0.y, dz0 = a0.z - b0.z, dw0 = a0.w - b0.w;
            float dx1 = a1.x - b1.x, dy1 = a1.y - b1.y, dz1 = a1.z - b1.z, dw1 = a1.w - b1.w;
            acc = fmaf(w.x, dx0 * dx0 + dy0 * dy0 + dz0 * dz0 + dw0 * dw0, acc);
            acc = fmaf(w.y, dx1 * dx1 + dy1 * dy1 + dz1 * dz1 + dw1 * dw1, acc);
        };

        if (nlocal > 0) issue(0, mb0, buf0, w0);
        int ph0 = 0, ph1 = 0, b = 0;
        while (b < nlocal) {
            if (b + 1 < nlocal) issue(b + 1, mb1, buf1, w1);
            mbar_wait(mb0, ph0); ph0 ^= 1;
            consume(buf0, w0);
            if (++b >= nlocal) break;
            if (b + 1 < nlocal) issue(b + 1, mb0, buf0, w0);
            mbar_wait(mb1, ph1); ph1 ^= 1;
            consume(buf1, w1);
            ++b;
        }
    }

    REDUCE_EPILOGUE(acc, out, inv_p);
}

// ================= fallback LDG kernel (proven 80.6us) =================
__global__ void __launch_bounds__(256)
mde_ldg_kernel(const float4* __restrict__ X,
               const int4* __restrict__ epairs,
               const float2* __restrict__ wpairs,
               int npairs,
               const int2* __restrict__ etail,
               const float* __restrict__ wtail,
               int p,
               float* __restrict__ out, float inv_p) {
    float acc = 0.0f;
    int stride = gridDim.x * blockDim.x;
    int tid = blockIdx.x * blockDim.x + threadIdx.x;
    for (int k = tid; k < npairs; k += stride) {
        int4   e = __ldcs(&epairs[k]);
        float2 w = __ldcs(&wpairs[k]);
        float4 a0 = __ldg(&X[e.x]);
        float4 b0 = __ldg(&X[e.y]);
        float4 a1 = __ldg(&X[e.z]);
        float4 b1 = __ldg(&X[e.w]);
        float dx0 = a0.x - b0.x, dy0 = a0.y - b0.y, dz0 = a0.z - b0.z, dw0 = a0.w - b0.w;
        float dx1 = a1.x - b1.x, dy1 = a1.y - b1.y, dz1 = a1.z - b1.z, dw1 = a1.w - b1.w;
        acc = fmaf(w.x, dx0 * dx0 + dy0 * dy0 + dz0 * dz0 + dw0 * dw0, acc);
        acc = fmaf(w.y, dx1 * dx1 + dy1 * dy1 + dz1 * dz1 + dw1 * dw1, acc);
    }
    int tail_base = npairs * 2;
    for (int k = tail_base + tid; k < p; k += stride) {
        int2 e = __ldg(&etail[k]);
        float4 a = __ldg(&X[e.x]);
        float4 b = __ldg(&X[e.y]);
        float dx = a.x - b.x, dy = a.y - b.y, dz = a.z - b.z, dw = a.w - b.w;
        acc = fmaf(__ldg(&wtail[k]), dx * dx + dy * dy + dz * dz + dw * dw, acc);
    }
    REDUCE_EPILOGUE(acc, out, inv_p);
}

// ================= host =================
extern "C" void kernel_launch(void* const* d_in, const int* in_sizes, int n_in,
                              void* d_out, int out_size) {
    const float4* X     = (const float4*)d_in[0];
    const int*    edges = (const int*)d_in[1];
    const float*  w     = (const float*)d_in[2];
    float*        out   = (float*)d_out;

    int p = in_sizes[2];
    float inv_p = 1.0f / (float)p;

    // Encode gather4 tensor map for X: f32 rank-2, global [4 x n_items],
    // box {4, 1} (gather4 = 4 independent single-row tile loads).
    bool tma_ok = false;
    CUtensorMap tmap;
    {
        typedef CUresult (*EncodeFn)(CUtensorMap*, CUtensorMapDataType, cuuint32_t,
                                     void*, const cuuint64_t*, const cuuint64_t*,
                                     const cuuint32_t*, const cuuint32_t*,
                                     CUtensorMapInterleave, CUtensorMapSwizzle,
                                     CUtensorMapL2promotion, CUtensorMapFloatOOBfill);
        EncodeFn fn = nullptr;
        cudaDriverEntryPointQueryResult qres;
        if (cudaGetDriverEntryPointByVersion("cuTensorMapEncodeTiled", (void**)&fn,
                                             12000, cudaEnableDefault, &qres) == cudaSuccess
            && fn != nullptr) {
            cuuint64_t gdim[2] = {4ull, (cuuint64_t)(in_sizes[0] / 4)};
            cuuint64_t gstr[1] = {16ull};
            cuuint32_t box[2]  = {4u, 1u};
            cuuint32_t est[2]  = {1u, 1u};
            CUresult r = fn(&tmap, CU_TENSOR_MAP_DATA_TYPE_FLOAT32, 2, (void*)X,
                            gdim, gstr, box, est,
                            CU_TENSOR_MAP_INTERLEAVE_NONE,
                            CU_TENSOR_MAP_SWIZZLE_NONE,
                            CU_TENSOR_MAP_L2_PROMOTION_L2_128B,
                            CU_TENSOR_MAP_FLOAT_OOB_FILL_NONE);
            tma_ok = (r == CUDA_SUCCESS);
        }
    }

    if (tma_ok && p >= 128) {
        int blocks = 888;   // 148 SMs x 6 CTAs (33KB smem/CTA)
        int nb_tma = (p / 2) / 64;          // TMA covers last 64*nb_tma edges
        int tma_edges = nb_tma * 64;
        int L = p - tma_edges;              // LDG region [0, L)
        int npairs_ldg = L / 2;
        int tail_lo = npairs_ldg * 2;       // leftover single edges in [tail_lo, L)
        mde_hybrid_kernel<<<blocks, 256>>>(tmap, X,
                                           (const int4*)edges, (const float2*)w,
                                           npairs_ldg, nb_tma,
                                           (const int2*)edges, w, tail_lo, L,
                                           out, inv_p);
    } else {
        int blocks = 1184;
        int npairs = p / 2;
        mde_ldg_kernel<<<blocks, 256>>>(X,
                                        (const int4*)edges, (const float2*)w, npairs,
                                        (const int2*)edges, w, p,
                                        out, inv_p);
    }
}

// round 8
// speedup vs baseline: 1.3023x; 1.3023x over previous
#include <cuda_runtime.h>
#include <cuda.h>
#include <cstdint>

// ---------------- scratch (no allocations allowed) ----------------
#define MAX_BLOCKS 2048
__device__ float g_partials[MAX_BLOCKS];
__device__ unsigned int g_ticket = 0;   // last block wraps it back to 0

// ---------------- small PTX helpers ----------------
__device__ __forceinline__ uint32_t smem_u32(const void* p) {
    uint32_t a;
    asm("{ .reg .u64 t; cvta.to.shared.u64 t, %1; cvt.u32.u64 %0, t; }"
        : "=r"(a) : "l"(p));
    return a;
}
#define MBARRIER_INIT(addr, cnt) \
    asm volatile("mbarrier.init.shared.b64 [%0], %1;" :: "r"(addr), "r"(cnt) : "memory")
#define MBARRIER_EXPECT_TX(addr, bytes) \
    asm volatile("mbarrier.arrive.expect_tx.shared.b64 _, [%0], %1;" :: "r"(addr), "r"(bytes) : "memory")
__device__ __forceinline__ void mbar_wait(uint32_t mbar, uint32_t parity) {
    asm volatile(
        "{\n\t"
        ".reg .pred P1;\n\t"
        "WAIT_LOOP_%=:\n\t"
        "mbarrier.try_wait.parity.acquire.cta.shared::cta.b64 P1, [%0], %1, 0x989680;\n\t"
        "@P1 bra.uni WAIT_DONE_%=;\n\t"
        "bra.uni WAIT_LOOP_%=;\n\t"
        "WAIT_DONE_%=:\n\t"
        "}"
        :: "r"(mbar), "r"(parity) : "memory");
}
// TMA tile::gather4 — fetch 4 rows (16B each, boxDim={4,1}) into SMEM (64B).
// dst MUST be 128B aligned.
__device__ __forceinline__ void tma_gather4(uint32_t dst_smem, const void* tmap,
                                            int r0, int r1, int r2, int r3,
                                            uint32_t mbar) {
    asm volatile(
        "cp.async.bulk.tensor.2d.shared::cta.global.tile::gather4.mbarrier::complete_tx::bytes "
        "[%0], [%1, {%2, %3, %4, %5, %6}], [%7];"
        :: "r"(dst_smem), "l"(tmap), "r"(0), "r"(r0), "r"(r1), "r"(r2), "r"(r3),
           "r"(mbar)
        : "memory");
}

// ---------------- shared reduction epilogue ----------------
#define REDUCE_EPILOGUE(acc, out, inv_p)                                        \
    do {                                                                        \
        _Pragma("unroll")                                                       \
        for (int off = 16; off > 0; off >>= 1)                                  \
            acc += __shfl_down_sync(0xffffffffu, acc, off);                     \
        __shared__ float warp_sums_[8];                                         \
        int lane_ = threadIdx.x & 31;                                           \
        int wid_  = threadIdx.x >> 5;                                           \
        if (lane_ == 0) warp_sums_[wid_] = acc;                                 \
        __syncthreads();                                                        \
        __shared__ bool is_last_;                                               \
        if (wid_ == 0) {                                                        \
            float v = (lane_ < 8) ? warp_sums_[lane_] : 0.0f;                   \
            _Pragma("unroll")                                                   \
            for (int off = 4; off > 0; off >>= 1)                               \
                v += __shfl_down_sync(0xffffffffu, v, off);                     \
            if (lane_ == 0) {                                                   \
                g_partials[blockIdx.x] = v;                                     \
                __threadfence();                                                \
                unsigned int done = atomicInc(&g_ticket, gridDim.x - 1);        \
                is_last_ = (done == gridDim.x - 1);                             \
            }                                                                   \
        }                                                                       \
        __syncthreads();                                                        \
        if (is_last_) {                                                         \
            double s = 0.0;                                                     \
            for (int i = threadIdx.x; i < (int)gridDim.x; i += blockDim.x)      \
                s += (double)g_partials[i];                                     \
            __shared__ double dsums_[8];                                        \
            _Pragma("unroll")                                                   \
            for (int off = 16; off > 0; off >>= 1)                              \
                s += __shfl_down_sync(0xffffffffu, s, off);                     \
            if (lane_ == 0) dsums_[wid_] = s;                                   \
            __syncthreads();                                                    \
            if (wid_ == 0) {                                                    \
                double t = (lane_ < 8) ? dsums_[lane_] : 0.0;                   \
                _Pragma("unroll")                                               \
                for (int off = 4; off > 0; off >>= 1)                           \
                    t += __shfl_down_sync(0xffffffffu, t, off);                 \
                if (lane_ == 0) out[0] = (float)(t * (double)inv_p);            \
            }                                                                   \
        }                                                                       \
    } while (0)

// ================= hybrid kernel, rate-balanced =================
// Warps 0-5 (75% of edges): LDG gathers via L1tex/LSU pipe.
// Warps 6-7 (25% of edges): TMA gather4 via the TMA engine,
//   64 edges per warp-batch, 2-stage double buffer per warp.
#define LDG_WARPS 6
#define TMA_WARPS 2
#define STRIDE_PER_LANE 128  // gather4 dst must be 128B aligned
#define STAGE_BYTES (32 * STRIDE_PER_LANE)   // 4096 per warp-stage

__global__ void __launch_bounds__(256)
mde_hybrid_kernel(const __grid_constant__ CUtensorMap tmap,
                  const float4* __restrict__ X,
                  const int4* __restrict__ epairs,
                  const float2* __restrict__ wpairs,
                  int npairs_ldg,          // int4 pairs in LDG region
                  int nb_tma,              // 64-edge batches in TMA region
                  const int2* __restrict__ etail,
                  const float* __restrict__ wtail,
                  int tail_lo, int tail_hi, // leftover single edges [lo, hi)
                  float* __restrict__ out, float inv_p) {
    __shared__ __align__(8)   uint64_t mbar[TMA_WARPS * 2];
    __shared__ __align__(128) char tbuf[TMA_WARPS][2][STAGE_BYTES];

    int tid  = threadIdx.x;
    int lane = tid & 31;
    int wid  = tid >> 5;
    float acc = 0.0f;

    if (wid < LDG_WARPS) {
        // ---------- LDG path ----------
        int t = blockIdx.x * (LDG_WARPS * 32) + wid * 32 + lane;
        int stride = gridDim.x * (LDG_WARPS * 32);
        for (int k = t; k < npairs_ldg; k += stride) {
            int4   e = __ldcs(&epairs[k]);
            float2 w = __ldcs(&wpairs[k]);
            float4 a0 = __ldg(&X[e.x]);
            float4 b0 = __ldg(&X[e.y]);
            float4 a1 = __ldg(&X[e.z]);
            float4 b1 = __ldg(&X[e.w]);
            float dx0 = a0.x - b0.x, dy0 = a0.y - b0.y, dz0 = a0.z - b0.z, dw0 = a0.w - b0.w;
            float dx1 = a1.x - b1.x, dy1 = a1.y - b1.y, dz1 = a1.z - b1.z, dw1 = a1.w - b1.w;
            acc = fmaf(w.x, dx0 * dx0 + dy0 * dy0 + dz0 * dz0 + dw0 * dw0, acc);
            acc = fmaf(w.y, dx1 * dx1 + dy1 * dy1 + dz1 * dz1 + dw1 * dw1, acc);
        }
        // leftover single edges (at most 1)
        for (int k = tail_lo + t; k < tail_hi; k += stride) {
            int2 e = __ldg(&etail[k]);
            float4 a = __ldg(&X[e.x]);
            float4 b = __ldg(&X[e.y]);
            float dx = a.x - b.x, dy = a.y - b.y, dz = a.z - b.z, dw = a.w - b.w;
            acc = fmaf(__ldg(&wtail[k]), dx * dx + dy * dy + dz * dz + dw * dw, acc);
        }
    } else {
        // ---------- TMA gather4 path ----------
        int tw = wid - LDG_WARPS;            // 0..1
        uint32_t mb0 = smem_u32(&mbar[tw * 2 + 0]);
        uint32_t mb1 = smem_u32(&mbar[tw * 2 + 1]);
        uint32_t buf0 = smem_u32(&tbuf[tw][0][0]) + (uint32_t)lane * STRIDE_PER_LANE;
        uint32_t buf1 = smem_u32(&tbuf[tw][1][0]) + (uint32_t)lane * STRIDE_PER_LANE;
        if (lane == 0) {
            MBARRIER_INIT(mb0, 1);
            MBARRIER_INIT(mb1, 1);
            asm volatile("fence.proxy.async.shared::cta;" ::: "memory");
        }
        __syncwarp();

        int W  = gridDim.x * TMA_WARPS;
        int gw = blockIdx.x * TMA_WARPS + tw;
        int nlocal = (gw < nb_tma) ? ((nb_tma - 1 - gw) / W + 1) : 0;

        float2 w0, w1;
        auto issue = [&](int bl, uint32_t mb, uint32_t bufaddr, float2& wreg) {
            int gb = gw + bl * W;
            int idx = npairs_ldg + gb * 32 + lane;   // int4 index into edge array
            if (lane == 0) MBARRIER_EXPECT_TX(mb, 32 * 64);
            __syncwarp();
            int4 e = __ldcs(&epairs[idx]);
            wreg = __ldcs(&wpairs[idx]);
            tma_gather4(bufaddr, (const void*)&tmap, e.x, e.y, e.z, e.w, mb);
        };
        auto consume = [&](uint32_t bufaddr, float2 w) {
            const float4* blk = (const float4*)__cvta_shared_to_generic(bufaddr);
            float4 a0 = blk[0], b0 = blk[1], a1 = blk[2], b1 = blk[3];
            float dx0 = a0.x - b0.x, dy0 = a0.y - b0.y, dz0 = a0.z - b0.z, dw0 = a0.w - b0.w;
            float dx1 = a1.x - b1.x, dy1 = a1.y - b1.y, dz1 = a1.z - b1.z, dw1 = a1.w - b1.w;
            acc = fmaf(w.x, dx0 * dx0 + dy0 * dy0 + dz0 * dz0 + dw0 * dw0, acc);
            acc = fmaf(w.y, dx1 * dx1 + dy1 * dy1 + dz1 * dz1 + dw1 * dw1, acc);
        };

        if (nlocal > 0) issue(0, mb0, buf0, w0);
        int ph0 = 0, ph1 = 0, b = 0;
        while (b < nlocal) {
            if (b + 1 < nlocal) issue(b + 1, mb1, buf1, w1);
            mbar_wait(mb0, ph0); ph0 ^= 1;
            consume(buf0, w0);
            if (++b >= nlocal) break;
            if (b + 1 < nlocal) issue(b + 1, mb0, buf0, w0);
            mbar_wait(mb1, ph1); ph1 ^= 1;
            consume(buf1, w1);
            ++b;
        }
    }

    REDUCE_EPILOGUE(acc, out, inv_p);
}

// ================= fallback LDG kernel (proven 80.6us) =================
__global__ void __launch_bounds__(256)
mde_ldg_kernel(const float4* __restrict__ X,
               const int4* __restrict__ epairs,
               const float2* __restrict__ wpairs,
               int npairs,
               const int2* __restrict__ etail,
               const float* __restrict__ wtail,
               int p,
               float* __restrict__ out, float inv_p) {
    float acc = 0.0f;
    int stride = gridDim.x * blockDim.x;
    int tid = blockIdx.x * blockDim.x + threadIdx.x;
    for (int k = tid; k < npairs; k += stride) {
        int4   e = __ldcs(&epairs[k]);
        float2 w = __ldcs(&wpairs[k]);
        float4 a0 = __ldg(&X[e.x]);
        float4 b0 = __ldg(&X[e.y]);
        float4 a1 = __ldg(&X[e.z]);
        float4 b1 = __ldg(&X[e.w]);
        float dx0 = a0.x - b0.x, dy0 = a0.y - b0.y, dz0 = a0.z - b0.z, dw0 = a0.w - b0.w;
        float dx1 = a1.x - b1.x, dy1 = a1.y - b1.y, dz1 = a1.z - b1.z, dw1 = a1.w - b1.w;
        acc = fmaf(w.x, dx0 * dx0 + dy0 * dy0 + dz0 * dz0 + dw0 * dw0, acc);
        acc = fmaf(w.y, dx1 * dx1 + dy1 * dy1 + dz1 * dz1 + dw1 * dw1, acc);
    }
    int tail_base = npairs * 2;
    for (int k = tail_base + tid; k < p; k += stride) {
        int2 e = __ldg(&etail[k]);
        float4 a = __ldg(&X[e.x]);
        float4 b = __ldg(&X[e.y]);
        float dx = a.x - b.x, dy = a.y - b.y, dz = a.z - b.z, dw = a.w - b.w;
        acc = fmaf(__ldg(&wtail[k]), dx * dx + dy * dy + dz * dz + dw * dw, acc);
    }
    REDUCE_EPILOGUE(acc, out, inv_p);
}

// ================= host =================
extern "C" void kernel_launch(void* const* d_in, const int* in_sizes, int n_in,
                              void* d_out, int out_size) {
    const float4* X     = (const float4*)d_in[0];
    const int*    edges = (const int*)d_in[1];
    const float*  w     = (const float*)d_in[2];
    float*        out   = (float*)d_out;

    int p = in_sizes[2];
    float inv_p = 1.0f / (float)p;

    // Encode gather4 tensor map for X: f32 rank-2, global [4 x n_items], box {4,1}.
    bool tma_ok = false;
    CUtensorMap tmap;
    {
        typedef CUresult (*EncodeFn)(CUtensorMap*, CUtensorMapDataType, cuuint32_t,
                                     void*, const cuuint64_t*, const cuuint64_t*,
                                     const cuuint32_t*, const cuuint32_t*,
                                     CUtensorMapInterleave, CUtensorMapSwizzle,
                                     CUtensorMapL2promotion, CUtensorMapFloatOOBfill);
        EncodeFn fn = nullptr;
        cudaDriverEntryPointQueryResult qres;
        if (cudaGetDriverEntryPointByVersion("cuTensorMapEncodeTiled", (void**)&fn,
                                             12000, cudaEnableDefault, &qres) == cudaSuccess
            && fn != nullptr) {
            cuuint64_t gdim[2] = {4ull, (cuuint64_t)(in_sizes[0] / 4)};
            cuuint64_t gstr[1] = {16ull};
            cuuint32_t box[2]  = {4u, 1u};
            cuuint32_t est[2]  = {1u, 1u};
            CUresult r = fn(&tmap, CU_TENSOR_MAP_DATA_TYPE_FLOAT32, 2, (void*)X,
                            gdim, gstr, box, est,
                            CU_TENSOR_MAP_INTERLEAVE_NONE,
                            CU_TENSOR_MAP_SWIZZLE_NONE,
                            CU_TENSOR_MAP_L2_PROMOTION_L2_128B,
                            CU_TENSOR_MAP_FLOAT_OOB_FILL_NONE);
            tma_ok = (r == CUDA_SUCCESS);
        }
    }

    if (tma_ok && p >= 512) {
        int blocks = 888;   // 148 SMs x 6 CTAs (reg-limited)
        // Rate-proportional split: TMA gets ~25% of edges (measured 0.148 vs
        // 0.476 edges/cyc/SM for TMA vs LDG paths).
        int nb_tma = (p / 4) / 64;          // 25% of edges in 64-edge batches
        int tma_edges = nb_tma * 64;
        int L = p - tma_edges;              // LDG region [0, L)
        int npairs_ldg = L / 2;
        int tail_lo = npairs_ldg * 2;       // leftover single edges in [tail_lo, L)
        mde_hybrid_kernel<<<blocks, 256>>>(tmap, X,
                                           (const int4*)edges, (const float2*)w,
                                           npairs_ldg, nb_tma,
                                           (const int2*)edges, w, tail_lo, L,
                                           out, inv_p);
    } else {
        int blocks = 1184;
        int npairs = p / 2;
        mde_ldg_kernel<<<blocks, 256>>>(X,
                                        (const int4*)edges, (const float2*)w, npairs,
                                        (const int2*)edges, w, p,
                                        out, inv_p);
    }
}